// round 3
// baseline (speedup 1.0000x reference)
#include <cuda_runtime.h>

// Shapes fixed by setup_inputs():
//   grid:     (N=2, C=12, D=8, Hg=16, Wg=16) float32
//   guidemap: (N=2, 1, H=1024, W=1024)       float32
//   out:      (N=2, C=12, H=1024, W=1024)    float32
#define Hh   1024
#define Ww   1024
#define HW   (Hh * Ww)
#define Cc   12
#define Dd   8
#define HG   16
#define WG   16

// SMEM layout: idx = c*CS + z*ZS + y*YS + x
// ZS = 16*16 + 4 = 260 -> z*ZS mod 32 = {0,4,8,...,28}: the 8 z-slices hit
// distinct banks, so per-warp z-divergent gathers are conflict-free.
#define YS   16
#define ZS   260
#define CS   (Dd * ZS)          // 2080
#define SMEM_FLOATS (Cc * CS)   // 24960 floats = 99840 bytes

#define TPB    1024
#define NBLK_X 74               // 74 blocks * 2 batches = 148 = one full wave

__global__ __launch_bounds__(TPB, 1)
void slice_operation_kernel(const float* __restrict__ grid,
                            const float* __restrict__ guide,
                            float* __restrict__ out)
{
    extern __shared__ float sg[];
    const int n = blockIdx.y;

    // ---- Stage grid[n] into padded SMEM (12*8*16*16 = 24576 floats) ----
    const float* gsrc = grid + (size_t)n * (Cc * Dd * HG * WG);
    for (int s = threadIdx.x; s < Cc * Dd * HG * WG; s += TPB) {
        int c   = s >> 11;      // / (8*16*16)
        int rem = s & 2047;
        int z   = rem >> 8;     // / (16*16)
        int yx  = rem & 255;    // y*16 + x (matches YS=16)
        sg[c * CS + z * ZS + yx] = gsrc[s];
    }
    __syncthreads();

    const float* gmap  = guide + (size_t)n * HW;
    float*       obase = out   + (size_t)n * (Cc * HW);

    const float sy = 15.0f / 1023.0f;   // (Hg-1)/(H-1)
    const float sx = 15.0f / 1023.0f;   // (Wg-1)/(W-1)

    for (int p = blockIdx.x * TPB + threadIdx.x; p < HW; p += NBLK_X * TPB) {
        const int y = p >> 10;
        const int x = p & 1023;

        // y/x interpolation (linspace(-1,1) -> iy = y*(Hg-1)/(H-1), always in range)
        float fy = (float)y * sy;
        float fx = (float)x * sx;
        int iy0 = min((int)fy, HG - 2);   // clamp floor; weight saturates at edge
        int ix0 = min((int)fx, WG - 2);
        float wy = fy - (float)iy0;
        float wx = fx - (float)ix0;

        // z from guidemap: iz = clip(g*(D-1), 0, D-1)
        float g  = __ldg(gmap + p);
        float fz = fminf(fmaxf(g * (float)(Dd - 1), 0.0f), (float)(Dd - 1));
        int iz0 = min((int)fz, Dd - 2);
        float wz = fz - (float)iz0;

        // 8 trilinear weights
        float wy0 = 1.0f - wy, wx0 = 1.0f - wx, wz0 = 1.0f - wz;
        float w00 = wy0 * wx0, w01 = wy0 * wx, w10 = wy * wx0, w11 = wy * wx;
        float a00 = w00 * wz0, a01 = w01 * wz0, a10 = w10 * wz0, a11 = w11 * wz0;
        float b00 = w00 * wz,  b01 = w01 * wz,  b10 = w10 * wz,  b11 = w11 * wz;

        const int base = iz0 * ZS + iy0 * YS + ix0;
        float* op = obase + p;

        #pragma unroll
        for (int c = 0; c < Cc; c++) {
            const float* s0 = sg + c * CS + base;
            float v = s0[0]       * a00 + s0[1]           * a01
                    + s0[YS]      * a10 + s0[YS + 1]      * a11
                    + s0[ZS]      * b00 + s0[ZS + 1]      * b01
                    + s0[ZS + YS] * b10 + s0[ZS + YS + 1] * b11;
            op[(size_t)c * HW] = v;
        }
    }
}

extern "C" void kernel_launch(void* const* d_in, const int* in_sizes, int n_in,
                              void* d_out, int out_size)
{
    const float* grid  = (const float*)d_in[0];
    const float* guide = (const float*)d_in[1];
    float*       out   = (float*)d_out;

    const size_t smem = SMEM_FLOATS * sizeof(float);   // 99,840 bytes
    cudaFuncSetAttribute(slice_operation_kernel,
                         cudaFuncAttributeMaxDynamicSharedMemorySize, (int)smem);

    dim3 gdim(NBLK_X, 2);
    slice_operation_kernel<<<gdim, TPB, smem>>>(grid, guide, out);
}